// round 16
// baseline (speedup 1.0000x reference)
#include <cuda_runtime.h>
#include <cuda_fp16.h>
#include <math.h>
#include <math_constants.h>
#include <cstdint>

#define HDIM 256
#define MAXB 1024
#define MAXN 32768

// ---------------------------------------------------------------------------
// Scratch (__device__ globals; no dynamic allocation allowed)
// ---------------------------------------------------------------------------
__device__ float g_q[(size_t)MAXB * HDIM];
__device__ float g_k[(size_t)MAXN * HDIM];
__device__ float g_v[(size_t)MAXN * HDIM];
__device__ __half g_wkt[HDIM * HDIM];   // W^T fp16: [n][k], k contiguous
__device__ __half g_wvt[HDIM * HDIM];
__device__ __half g_wqt[HDIM * HDIM];

// Tiled transpose + fp16 convert: out[n][k] = fp16(W[k][n]).
__global__ void __launch_bounds__(256) convert_w_kernel(
    const float* __restrict__ Wk, const float* __restrict__ Wv, const float* __restrict__ Wq,
    __half* __restrict__ ok, __half* __restrict__ ov, __half* __restrict__ oq)
{
    __shared__ float tile[32][33];
    const float* W = (blockIdx.z == 0) ? Wk : (blockIdx.z == 1 ? Wv : Wq);
    __half* o = (blockIdx.z == 0) ? ok : (blockIdx.z == 1 ? ov : oq);

    const int k0 = blockIdx.y * 32;
    const int n0 = blockIdx.x * 32;
    const int tx = threadIdx.x & 31;
    const int ty = threadIdx.x >> 5;

    #pragma unroll
    for (int r = 0; r < 32; r += 8)
        tile[ty + r][tx] = W[(size_t)(k0 + ty + r) * HDIM + n0 + tx];
    __syncthreads();
    #pragma unroll
    for (int r = 0; r < 32; r += 8)
        o[(size_t)(n0 + ty + r) * HDIM + k0 + tx] = __float2half(tile[tx][ty + r]);
}

// ---------------------------------------------------------------------------
// Dual GEMM kernel: ONE CTA computes K[128,128] AND V[128,128] tiles sharing
// a single A (social) fp32 tile. 512 threads: warps 0-7 -> K, warps 8-15 -> V.
// Within each half: 4(m) x 2(n) warps, warp tile 32x64 (proven geometry).
// fp16 mma.sync.m16n8k16, cp.async double buffered, in-register A cvt,
// ldmatrix.x4 for B. Q rides on grid z=1 (B=Wq, V-half idles).
// ---------------------------------------------------------------------------
#define KC 64                         // K-chunk
#define NCHUNK (HDIM / KC)            // 4
#define SROWF 68                      // fp32 A smem row stride (floats); 272 B
#define SROWB 72                      // fp16 B smem row stride (elems); 144 B
#define A_TILE_BYTES (128 * SROWF * 4)        // 34816
#define B_TILE_BYTES (128 * SROWB * 2)        // 18432
#define STAGE_BYTES (A_TILE_BYTES + 2 * B_TILE_BYTES)   // 71680
#define SMEM_BYTES (2 * STAGE_BYTES)                    // 143360 (1 CTA/SM)

__device__ __forceinline__ void mma_f16(float* d, const uint32_t* a, uint32_t b0, uint32_t b1) {
    asm volatile(
        "mma.sync.aligned.m16n8k16.row.col.f32.f16.f16.f32 "
        "{%0,%1,%2,%3}, {%4,%5,%6,%7}, {%8,%9}, {%0,%1,%2,%3};\n"
        : "+f"(d[0]), "+f"(d[1]), "+f"(d[2]), "+f"(d[3])
        : "r"(a[0]), "r"(a[1]), "r"(a[2]), "r"(a[3]), "r"(b0), "r"(b1));
}
__device__ __forceinline__ void ldmatrix_x4(uint32_t& r0, uint32_t& r1, uint32_t& r2, uint32_t& r3,
                                            uint32_t smem_addr) {
    asm volatile("ldmatrix.sync.aligned.m8n8.x4.shared.b16 {%0,%1,%2,%3}, [%4];\n"
                 : "=r"(r0), "=r"(r1), "=r"(r2), "=r"(r3) : "r"(smem_addr));
}
__device__ __forceinline__ void cp_async16(uint32_t smem_dst, const void* gsrc) {
    asm volatile("cp.async.cg.shared.global [%0], [%1], 16;\n" :: "r"(smem_dst), "l"(gsrc));
}
__device__ __forceinline__ uint32_t cvt2(float2 f) {
    __half2 h = __floats2half2_rn(f.x, f.y);
    return *reinterpret_cast<uint32_t*>(&h);
}

__global__ void __launch_bounds__(512, 1) fused_mma_kernel(
    const float* __restrict__ social, const float* __restrict__ enc,
    const float* __restrict__ bk, const float* __restrict__ bv,
    const float* __restrict__ bq, float inv_sqrt_d, int qm_tiles)
{
    extern __shared__ char smraw[];

    const int z = blockIdx.z;            // 0: K+V (A=social), 1: Q (A=enc)
    if (z == 1 && blockIdx.y >= qm_tiles) return;

    const int tid = threadIdx.x;
    const int wid = tid >> 5;
    const int lane = tid & 31;
    const int grp = lane >> 2;
    const int qid = lane & 3;
    const int half = wid >> 3;           // 0: K (or Q), 1: V (idle when z==1)
    const int hw = wid & 7;              // warp id within half
    const int warp_m = hw & 3;           // 4 warps along m
    const int warp_n = hw >> 2;          // 2 warps along n

    const int bm = blockIdx.y, bn = blockIdx.x;
    const bool q_plane = (z == 1);
    const bool active = !(q_plane && half == 1);

    const float* gA = q_plane ? enc : social;
    const __half* myB = q_plane ? g_wqt : (half ? g_wvt : g_wkt);
    const float* bias = q_plane ? bq : (half ? bv : bk);
    float* C = q_plane ? g_q : (half ? g_v : g_k);
    const float scale = q_plane ? inv_sqrt_d : 1.0f;

    uint32_t smem_u32;
    {
        uint64_t t = __cvta_generic_to_shared(smraw);
        smem_u32 = (uint32_t)t;
    }

    // ldmatrix per-lane offset within a (16n x 16k) B block
    const int ldm_n = ((lane >> 4) & 1) * 8 + (lane & 7);
    const int ldm_k = ((lane >> 3) & 1) * 8;
    const uint32_t ldm_lane_off = (uint32_t)(ldm_n * SROWB + ldm_k) * 2;

    auto prefetch = [&](int s, int c) {
        uint32_t stage = smem_u32 + s * STAGE_BYTES;
        // A: 2048 16B segs -> 4 per thread (512 threads)
        const float* srcA = gA + (size_t)(bm * 128) * HDIM + c * KC;
        #pragma unroll
        for (int u = 0; u < 4; u++) {
            int seg = u * 512 + tid;
            int row = seg >> 4, cs = seg & 15;
            cp_async16(stage + row * (SROWF * 4) + cs * 16,
                       srcA + (size_t)row * HDIM + cs * 4);
        }
        // Bk (or Bq): 1024 segs -> 2 per thread
        const __half* srcBk = (q_plane ? g_wqt : g_wkt) + (size_t)(bn * 128) * HDIM + c * KC;
        uint32_t dk = stage + A_TILE_BYTES;
        #pragma unroll
        for (int u = 0; u < 2; u++) {
            int seg = u * 512 + tid;
            int row = seg >> 3, cs = seg & 7;
            cp_async16(dk + row * (SROWB * 2) + cs * 16,
                       srcBk + (size_t)row * HDIM + cs * 8);
        }
        // Bv: 2 per thread (skip on Q plane)
        if (!q_plane) {
            const __half* srcBv = g_wvt + (size_t)(bn * 128) * HDIM + c * KC;
            uint32_t dv = stage + A_TILE_BYTES + B_TILE_BYTES;
            #pragma unroll
            for (int u = 0; u < 2; u++) {
                int seg = u * 512 + tid;
                int row = seg >> 3, cs = seg & 7;
                cp_async16(dv + row * (SROWB * 2) + cs * 16,
                           srcBv + (size_t)row * HDIM + cs * 8);
            }
        }
        asm volatile("cp.async.commit_group;\n");
    };

    float acc[2][8][4] = {};

    prefetch(0, 0);

    for (int c = 0; c < NCHUNK; c++) {
        if (c + 1 < NCHUNK) {
            prefetch((c + 1) & 1, c + 1);
            asm volatile("cp.async.wait_group 1;\n");
        } else {
            asm volatile("cp.async.wait_group 0;\n");
        }
        __syncthreads();

        if (active) {
            const char* st = smraw + (c & 1) * STAGE_BYTES;
            const float* sA = (const float*)st;
            const uint32_t sB_u32 = smem_u32 + (c & 1) * STAGE_BYTES + A_TILE_BYTES
                                  + half * B_TILE_BYTES;

            #pragma unroll
            for (int ks = 0; ks < KC / 16; ks++) {
                const int k0 = ks * 16;
                uint32_t af[2][4];
                #pragma unroll
                for (int mi = 0; mi < 2; mi++) {
                    const float* a0 = sA + (warp_m * 32 + mi * 16 + grp) * SROWF + k0 + 2 * qid;
                    af[mi][0] = cvt2(*(const float2*)(a0));
                    af[mi][1] = cvt2(*(const float2*)(a0 + 8 * SROWF));
                    af[mi][2] = cvt2(*(const float2*)(a0 + 8));
                    af[mi][3] = cvt2(*(const float2*)(a0 + 8 * SROWF + 8));
                }
                #pragma unroll
                for (int nbp = 0; nbp < 4; nbp++) {
                    uint32_t baddr = sB_u32 + ldm_lane_off
                                   + (uint32_t)((warp_n * 64 + nbp * 16) * SROWB + k0) * 2;
                    uint32_t r0, r1, r2, r3;
                    ldmatrix_x4(r0, r1, r2, r3, baddr);
                    #pragma unroll
                    for (int mi = 0; mi < 2; mi++) {
                        mma_f16(acc[mi][nbp * 2 + 0], af[mi], r0, r1);
                        mma_f16(acc[mi][nbp * 2 + 1], af[mi], r2, r3);
                    }
                }
            }
        }
        __syncthreads();
    }

    if (!active) return;

    // Epilogue: bias + relu (+ post-relu scale), fp32 stores.
    #pragma unroll
    for (int mi = 0; mi < 2; mi++) {
        const int row = bm * 128 + warp_m * 32 + mi * 16 + grp;
        #pragma unroll
        for (int nb = 0; nb < 8; nb++) {
            const int col = bn * 128 + warp_n * 64 + nb * 8 + 2 * qid;
            float2 bz = *(const float2*)(bias + col);
            float2 o0, o1;
            o0.x = fmaxf(acc[mi][nb][0] + bz.x, 0.f) * scale;
            o0.y = fmaxf(acc[mi][nb][1] + bz.y, 0.f) * scale;
            o1.x = fmaxf(acc[mi][nb][2] + bz.x, 0.f) * scale;
            o1.y = fmaxf(acc[mi][nb][3] + bz.y, 0.f) * scale;
            *(float2*)(C + (size_t)row * HDIM + col) = o0;
            *(float2*)(C + (size_t)(row + 8) * HDIM + col) = o1;
        }
    }
}

// ---------------------------------------------------------------------------
// Windowed attention (unchanged — measured ~14us).
// ---------------------------------------------------------------------------
__global__ void __launch_bounds__(256) attn_kernel(
    const int* __restrict__ starts, const int* __restrict__ ends, float* __restrict__ out)
{
    const int i = blockIdx.x;
    const int tid = threadIdx.x;
    const int warp = tid >> 5, lane = tid & 31;
    __shared__ float qs[HDIM];
    __shared__ float sc[72];
    __shared__ float redbuf[8];

    qs[tid] = g_q[(size_t)i * HDIM + tid];
    if (tid < 72) sc[tid] = 0.f;
    const int s = starts[i];
    const int nn = ends[i] - s;   // 1..63
    __syncthreads();

    {
        const float4* qrow = (const float4*)qs + lane * 2;
        const float4 q0 = qrow[0], q1 = qrow[1];
        int j = warp;
        for (; j + 8 < nn; j += 16) {
            const float4* ka = (const float4*)(g_k + (size_t)(s + j) * HDIM) + lane * 2;
            const float4* kb = (const float4*)(g_k + (size_t)(s + j + 8) * HDIM) + lane * 2;
            float4 a0 = ka[0], a1 = ka[1];
            float4 b0 = kb[0], b1 = kb[1];
            float accA = a0.x * q0.x;
            float accB = b0.x * q0.x;
            accA = fmaf(a0.y, q0.y, accA);  accB = fmaf(b0.y, q0.y, accB);
            accA = fmaf(a0.z, q0.z, accA);  accB = fmaf(b0.z, q0.z, accB);
            accA = fmaf(a0.w, q0.w, accA);  accB = fmaf(b0.w, q0.w, accB);
            accA = fmaf(a1.x, q1.x, accA);  accB = fmaf(b1.x, q1.x, accB);
            accA = fmaf(a1.y, q1.y, accA);  accB = fmaf(b1.y, q1.y, accB);
            accA = fmaf(a1.z, q1.z, accA);  accB = fmaf(b1.z, q1.z, accB);
            accA = fmaf(a1.w, q1.w, accA);  accB = fmaf(b1.w, q1.w, accB);
            #pragma unroll
            for (int o = 16; o; o >>= 1) {
                accA += __shfl_xor_sync(0xffffffffu, accA, o);
                accB += __shfl_xor_sync(0xffffffffu, accB, o);
            }
            if (lane == 0) { sc[j] = accA; sc[j + 8] = accB; }
        }
        if (j < nn) {
            const float4* krow = (const float4*)(g_k + (size_t)(s + j) * HDIM) + lane * 2;
            float4 k0 = krow[0], k1 = krow[1];
            float acc = k0.x * q0.x;
            acc = fmaf(k0.y, q0.y, acc);
            acc = fmaf(k0.z, q0.z, acc);
            acc = fmaf(k0.w, q0.w, acc);
            acc = fmaf(k1.x, q1.x, acc);
            acc = fmaf(k1.y, q1.y, acc);
            acc = fmaf(k1.z, q1.z, acc);
            acc = fmaf(k1.w, q1.w, acc);
            #pragma unroll
            for (int o = 16; o; o >>= 1) acc += __shfl_xor_sync(0xffffffffu, acc, o);
            if (lane == 0) sc[j] = acc;
        }
    }
    __syncthreads();

    float x = -CUDART_INF_F;
    if (tid < 64) {
        x = (tid < nn) ? sc[tid] : -CUDART_INF_F;
        float m = x;
        #pragma unroll
        for (int o = 16; o; o >>= 1) m = fmaxf(m, __shfl_xor_sync(0xffffffffu, m, o));
        if (lane == 0) redbuf[warp] = m;
    }
    __syncthreads();
    const float m = fmaxf(redbuf[0], redbuf[1]);
    float p = 0.f;
    if (tid < 64) {
        p = (tid < nn) ? expf(x - m) : 0.f;
        float ssum = p;
        #pragma unroll
        for (int o = 16; o; o >>= 1) ssum += __shfl_xor_sync(0xffffffffu, ssum, o);
        if (lane == 0) redbuf[4 + warp] = ssum;
    }
    __syncthreads();
    const float inv = 1.f / (redbuf[4] + redbuf[5]);
    if (tid < 64) sc[tid] = p * inv;
    __syncthreads();

    const float* vbase = g_v + (size_t)s * HDIM + tid;
    const int jmax = nn - 1;
    float acc = 0.f;
    for (int j = 0; j < nn; j += 8) {
        float w[8], v[8];
        #pragma unroll
        for (int u = 0; u < 8; u++) {
            int jj = min(j + u, jmax);
            w[u] = sc[j + u];
            v[u] = vbase[(size_t)jj * HDIM];
        }
        #pragma unroll
        for (int u = 0; u < 8; u++) acc = fmaf(w[u], v[u], acc);
    }
    out[(size_t)i * HDIM + tid] = acc;
}

// ---------------------------------------------------------------------------
extern "C" void kernel_launch(void* const* d_in, const int* in_sizes, int n_in,
                              void* d_out, int out_size)
{
    const float* enc    = (const float*)d_in[0];
    const float* social = (const float*)d_in[1];
    const int*   starts = (const int*)  d_in[2];
    const int*   ends   = (const int*)  d_in[3];
    const float* Wq     = (const float*)d_in[4];
    const float* bq     = (const float*)d_in[5];
    const float* Wk     = (const float*)d_in[6];
    const float* bk     = (const float*)d_in[7];
    const float* Wv     = (const float*)d_in[8];
    const float* bv     = (const float*)d_in[9];
    float* out = (float*)d_out;

    const int B = in_sizes[0] / HDIM;
    const int N = in_sizes[1] / HDIM;

    __half *wk16, *wv16, *wq16;
    cudaGetSymbolAddress((void**)&wk16, g_wkt);
    cudaGetSymbolAddress((void**)&wv16, g_wvt);
    cudaGetSymbolAddress((void**)&wq16, g_wqt);

    cudaFuncSetAttribute(fused_mma_kernel, cudaFuncAttributeMaxDynamicSharedMemorySize, SMEM_BYTES);

    const float inv_sqrt_d = 1.0f / sqrtf((float)HDIM);

    // 1. Tiled transpose+convert Wk, Wv, Wq to fp16
    convert_w_kernel<<<dim3(HDIM / 32, HDIM / 32, 3), 256>>>(Wk, Wv, Wq, wk16, wv16, wq16);
    // 2. K+V (shared A tile) and Q in ONE launch (z=0: K+V, z=1: Q)
    fused_mma_kernel<<<dim3(HDIM / 128, N / 128, 2), 512, SMEM_BYTES>>>(
        social, enc, bk, bv, bq, inv_sqrt_d, B / 128);
    // 3. Windowed attention
    attn_kernel<<<B, 256>>>(starts, ends, out);
}

// round 17
// speedup vs baseline: 1.0586x; 1.0586x over previous
#include <cuda_runtime.h>
#include <cuda_fp16.h>
#include <math.h>
#include <math_constants.h>
#include <cstdint>

#define HDIM 256
#define MAXB 1024
#define MAXN 32768

// ---------------------------------------------------------------------------
// Scratch (__device__ globals; no dynamic allocation allowed)
// ---------------------------------------------------------------------------
__device__ float g_q[(size_t)MAXB * HDIM];
__device__ float g_k[(size_t)MAXN * HDIM];
__device__ float g_v[(size_t)MAXN * HDIM];
__device__ __half g_wkt[HDIM * HDIM];   // W^T fp16: [n][k], k contiguous
__device__ __half g_wvt[HDIM * HDIM];
__device__ __half g_wqt[HDIM * HDIM];

// Tiled transpose + fp16 convert: out[n][k] = fp16(W[k][n]).
// float4 reads, half2x2 writes; 32x32 tiles, conflict-free padded smem.
__global__ void __launch_bounds__(256) convert_w_kernel(
    const float* __restrict__ Wk, const float* __restrict__ Wv, const float* __restrict__ Wq,
    __half* __restrict__ ok, __half* __restrict__ ov, __half* __restrict__ oq)
{
    __shared__ float tile[32][36];
    const float* W = (blockIdx.z == 0) ? Wk : (blockIdx.z == 1 ? Wv : Wq);
    __half* o = (blockIdx.z == 0) ? ok : (blockIdx.z == 1 ? ov : oq);

    const int k0 = blockIdx.y * 32;
    const int n0 = blockIdx.x * 32;

    // Read: 32 rows x 8 float4 = 256 vector loads, one per thread.
    {
        const int r = threadIdx.x >> 3;        // 0..31
        const int c4 = (threadIdx.x & 7) * 4;  // 0,4,..28
        float4 v = *(const float4*)(W + (size_t)(k0 + r) * HDIM + n0 + c4);
        tile[r][c4 + 0] = v.x;
        tile[r][c4 + 1] = v.y;
        tile[r][c4 + 2] = v.z;
        tile[r][c4 + 3] = v.w;
    }
    __syncthreads();

    // Write transposed: 32 n-rows x 8 half4-groups, one per thread.
    {
        const int n = threadIdx.x >> 3;        // 0..31
        const int c4 = (threadIdx.x & 7) * 4;  // k offset group
        __half h[4];
        h[0] = __float2half(tile[c4 + 0][n]);
        h[1] = __float2half(tile[c4 + 1][n]);
        h[2] = __float2half(tile[c4 + 2][n]);
        h[3] = __float2half(tile[c4 + 3][n]);
        *(uint2*)(o + (size_t)(n0 + n) * HDIM + k0 + c4) = *(const uint2*)h;
    }
}

// ---------------------------------------------------------------------------
// Shared GEMM tile body: C[128,128] tile = relu(A_fp32 @ W16^T + bias)*scale
// fp16 mma.sync.m16n8k16, cp.async double buffered, in-register A cvt,
// ldmatrix.x4 for B fragments. 256 threads, 8 warps = 4(m) x 2(n).
// ---------------------------------------------------------------------------
#define KC 64                         // K-chunk
#define NCHUNK (HDIM / KC)            // 4
#define SROWF 68                      // fp32 A smem row stride (floats); 272 B
#define SROWB 72                      // fp16 B smem row stride (elems); 144 B
#define A_TILE_BYTES (128 * SROWF * 4)        // 34816
#define B_TILE_BYTES (128 * SROWB * 2)        // 18432
#define STAGE_BYTES (A_TILE_BYTES + B_TILE_BYTES)   // 53248
#define SMEM_BYTES (2 * STAGE_BYTES)                // 106496 (2 CTAs/SM)

__device__ __forceinline__ void mma_f16(float* d, const uint32_t* a, uint32_t b0, uint32_t b1) {
    asm volatile(
        "mma.sync.aligned.m16n8k16.row.col.f32.f16.f16.f32 "
        "{%0,%1,%2,%3}, {%4,%5,%6,%7}, {%8,%9}, {%0,%1,%2,%3};\n"
        : "+f"(d[0]), "+f"(d[1]), "+f"(d[2]), "+f"(d[3])
        : "r"(a[0]), "r"(a[1]), "r"(a[2]), "r"(a[3]), "r"(b0), "r"(b1));
}
__device__ __forceinline__ void ldmatrix_x4(uint32_t& r0, uint32_t& r1, uint32_t& r2, uint32_t& r3,
                                            uint32_t smem_addr) {
    asm volatile("ldmatrix.sync.aligned.m8n8.x4.shared.b16 {%0,%1,%2,%3}, [%4];\n"
                 : "=r"(r0), "=r"(r1), "=r"(r2), "=r"(r3) : "r"(smem_addr));
}
__device__ __forceinline__ void cp_async16(uint32_t smem_dst, const void* gsrc) {
    asm volatile("cp.async.cg.shared.global [%0], [%1], 16;\n" :: "r"(smem_dst), "l"(gsrc));
}
__device__ __forceinline__ uint32_t cvt2(float2 f) {
    __half2 h = __floats2half2_rn(f.x, f.y);
    return *reinterpret_cast<uint32_t*>(&h);
}

__device__ __forceinline__ void gemm_tile_body(
    const float* __restrict__ gA,
    const __half* __restrict__ gB,
    const float* __restrict__ bias, float* __restrict__ C, float scale,
    int bm, int bn, char* smraw)
{
    const int tid = threadIdx.x;
    const int wid = tid >> 5;
    const int lane = tid & 31;
    const int grp = lane >> 2;      // 0..7
    const int qid = lane & 3;       // 0..3
    const int warp_m = wid & 3;     // 4 warps along m (32 rows each)
    const int warp_n = wid >> 2;    // 2 warps along n (64 cols each)

    uint32_t smem_u32;
    {
        uint64_t t = __cvta_generic_to_shared(smraw);
        smem_u32 = (uint32_t)t;
    }

    // ldmatrix per-lane address offset within a (16n x 16k) B block
    const int ldm_n = ((lane >> 4) & 1) * 8 + (lane & 7);
    const int ldm_k = ((lane >> 3) & 1) * 8;
    const uint32_t ldm_lane_off = (uint32_t)(ldm_n * SROWB + ldm_k) * 2;

    auto prefetch = [&](int s, int c) {
        uint32_t stage = smem_u32 + s * STAGE_BYTES;
        const float* srcA = gA + (size_t)(bm * 128) * HDIM + c * KC;
        #pragma unroll
        for (int u = 0; u < 8; u++) {
            int seg = u * 256 + tid;
            int row = seg >> 4, cs = seg & 15;
            cp_async16(stage + row * (SROWF * 4) + cs * 16,
                       srcA + (size_t)row * HDIM + cs * 4);
        }
        const __half* srcB = gB + (size_t)(bn * 128) * HDIM + c * KC;
        uint32_t dstb = stage + A_TILE_BYTES;
        #pragma unroll
        for (int u = 0; u < 4; u++) {
            int seg = u * 256 + tid;
            int row = seg >> 3, cs = seg & 7;
            cp_async16(dstb + row * (SROWB * 2) + cs * 16,
                       srcB + (size_t)row * HDIM + cs * 8);
        }
        asm volatile("cp.async.commit_group;\n");
    };

    float acc[2][8][4] = {};

    prefetch(0, 0);

    for (int c = 0; c < NCHUNK; c++) {
        if (c + 1 < NCHUNK) {
            prefetch((c + 1) & 1, c + 1);
            asm volatile("cp.async.wait_group 1;\n");
        } else {
            asm volatile("cp.async.wait_group 0;\n");
        }
        __syncthreads();

        const char* st = smraw + (c & 1) * STAGE_BYTES;
        const float* sA = (const float*)st;
        const uint32_t sB_u32 = smem_u32 + (c & 1) * STAGE_BYTES + A_TILE_BYTES;

        #pragma unroll
        for (int ks = 0; ks < KC / 16; ks++) {
            const int k0 = ks * 16;
            uint32_t af[2][4];
            #pragma unroll
            for (int mi = 0; mi < 2; mi++) {
                const float* a0 = sA + (warp_m * 32 + mi * 16 + grp) * SROWF + k0 + 2 * qid;
                af[mi][0] = cvt2(*(const float2*)(a0));              // row, k
                af[mi][1] = cvt2(*(const float2*)(a0 + 8 * SROWF));  // row+8, k
                af[mi][2] = cvt2(*(const float2*)(a0 + 8));          // row, k+8
                af[mi][3] = cvt2(*(const float2*)(a0 + 8 * SROWF + 8));
            }
            #pragma unroll
            for (int nbp = 0; nbp < 4; nbp++) {   // pairs of nb tiles: 16 n-rows each
                uint32_t baddr = sB_u32 + ldm_lane_off
                               + (uint32_t)((warp_n * 64 + nbp * 16) * SROWB + k0) * 2;
                uint32_t r0, r1, r2, r3;
                ldmatrix_x4(r0, r1, r2, r3, baddr);
                #pragma unroll
                for (int mi = 0; mi < 2; mi++) {
                    mma_f16(acc[mi][nbp * 2 + 0], af[mi], r0, r1);
                    mma_f16(acc[mi][nbp * 2 + 1], af[mi], r2, r3);
                }
            }
        }
        __syncthreads();   // readers done before next iteration's prefetch overwrites
    }

    // Epilogue: bias + relu (+ post-relu scale), fp32 stores.
    #pragma unroll
    for (int mi = 0; mi < 2; mi++) {
        const int row = bm * 128 + warp_m * 32 + mi * 16 + grp;
        #pragma unroll
        for (int nb = 0; nb < 8; nb++) {
            const int col = bn * 128 + warp_n * 64 + nb * 8 + 2 * qid;
            float2 bz = *(const float2*)(bias + col);
            float2 o0, o1;
            o0.x = fmaxf(acc[mi][nb][0] + bz.x, 0.f) * scale;
            o0.y = fmaxf(acc[mi][nb][1] + bz.y, 0.f) * scale;
            o1.x = fmaxf(acc[mi][nb][2] + bz.x, 0.f) * scale;
            o1.y = fmaxf(acc[mi][nb][3] + bz.y, 0.f) * scale;
            *(float2*)(C + (size_t)row * HDIM + col) = o0;
            *(float2*)(C + (size_t)(row + 8) * HDIM + col) = o1;
        }
    }
}

// Fused K/V/Q GEMM: grid (2 n-tiles, 256 m-tiles, 3 planes); 2 CTAs/SM.
__global__ void __launch_bounds__(256, 2) fused_mma_kernel(
    const float* __restrict__ social, const float* __restrict__ enc,
    const float* __restrict__ bk, const float* __restrict__ bv,
    const float* __restrict__ bq, float inv_sqrt_d, int qm_tiles)
{
    extern __shared__ char smraw[];
    const int z = blockIdx.z;
    if (z == 2) {
        if (blockIdx.y >= qm_tiles) return;
        gemm_tile_body(enc, g_wqt, bq, g_q, inv_sqrt_d, blockIdx.y, blockIdx.x, smraw);
    } else {
        gemm_tile_body(social, z ? g_wvt : g_wkt, z ? bv : bk, z ? g_v : g_k, 1.0f,
                       blockIdx.y, blockIdx.x, smraw);
    }
}

// ---------------------------------------------------------------------------
// Windowed attention. Score phase: unroll x2 over K rows (MLP 4).
// V phase: unroll x8, clamped rows, zero-padded weights (nn <= 63).
// ---------------------------------------------------------------------------
__global__ void __launch_bounds__(256) attn_kernel(
    const int* __restrict__ starts, const int* __restrict__ ends, float* __restrict__ out)
{
    const int i = blockIdx.x;
    const int tid = threadIdx.x;
    const int warp = tid >> 5, lane = tid & 31;
    __shared__ float qs[HDIM];
    __shared__ float sc[72];
    __shared__ float redbuf[8];

    qs[tid] = g_q[(size_t)i * HDIM + tid];
    if (tid < 72) sc[tid] = 0.f;
    const int s = starts[i];
    const int nn = ends[i] - s;   // 1..63
    __syncthreads();

    {
        const float4* qrow = (const float4*)qs + lane * 2;
        const float4 q0 = qrow[0], q1 = qrow[1];
        int j = warp;
        for (; j + 8 < nn; j += 16) {
            const float4* ka = (const float4*)(g_k + (size_t)(s + j) * HDIM) + lane * 2;
            const float4* kb = (const float4*)(g_k + (size_t)(s + j + 8) * HDIM) + lane * 2;
            float4 a0 = ka[0], a1 = ka[1];
            float4 b0 = kb[0], b1 = kb[1];
            float accA = a0.x * q0.x;
            float accB = b0.x * q0.x;
            accA = fmaf(a0.y, q0.y, accA);  accB = fmaf(b0.y, q0.y, accB);
            accA = fmaf(a0.z, q0.z, accA);  accB = fmaf(b0.z, q0.z, accB);
            accA = fmaf(a0.w, q0.w, accA);  accB = fmaf(b0.w, q0.w, accB);
            accA = fmaf(a1.x, q1.x, accA);  accB = fmaf(b1.x, q1.x, accB);
            accA = fmaf(a1.y, q1.y, accA);  accB = fmaf(b1.y, q1.y, accB);
            accA = fmaf(a1.z, q1.z, accA);  accB = fmaf(b1.z, q1.z, accB);
            accA = fmaf(a1.w, q1.w, accA);  accB = fmaf(b1.w, q1.w, accB);
            #pragma unroll
            for (int o = 16; o; o >>= 1) {
                accA += __shfl_xor_sync(0xffffffffu, accA, o);
                accB += __shfl_xor_sync(0xffffffffu, accB, o);
            }
            if (lane == 0) { sc[j] = accA; sc[j + 8] = accB; }
        }
        if (j < nn) {
            const float4* krow = (const float4*)(g_k + (size_t)(s + j) * HDIM) + lane * 2;
            float4 k0 = krow[0], k1 = krow[1];
            float acc = k0.x * q0.x;
            acc = fmaf(k0.y, q0.y, acc);
            acc = fmaf(k0.z, q0.z, acc);
            acc = fmaf(k0.w, q0.w, acc);
            acc = fmaf(k1.x, q1.x, acc);
            acc = fmaf(k1.y, q1.y, acc);
            acc = fmaf(k1.z, q1.z, acc);
            acc = fmaf(k1.w, q1.w, acc);
            #pragma unroll
            for (int o = 16; o; o >>= 1) acc += __shfl_xor_sync(0xffffffffu, acc, o);
            if (lane == 0) sc[j] = acc;
        }
    }
    __syncthreads();

    float x = -CUDART_INF_F;
    if (tid < 64) {
        x = (tid < nn) ? sc[tid] : -CUDART_INF_F;
        float m = x;
        #pragma unroll
        for (int o = 16; o; o >>= 1) m = fmaxf(m, __shfl_xor_sync(0xffffffffu, m, o));
        if (lane == 0) redbuf[warp] = m;
    }
    __syncthreads();
    const float m = fmaxf(redbuf[0], redbuf[1]);
    float p = 0.f;
    if (tid < 64) {
        p = (tid < nn) ? expf(x - m) : 0.f;
        float ssum = p;
        #pragma unroll
        for (int o = 16; o; o >>= 1) ssum += __shfl_xor_sync(0xffffffffu, ssum, o);
        if (lane == 0) redbuf[4 + warp] = ssum;
    }
    __syncthreads();
    const float inv = 1.f / (redbuf[4] + redbuf[5]);
    if (tid < 64) sc[tid] = p * inv;
    __syncthreads();

    const float* vbase = g_v + (size_t)s * HDIM + tid;
    const int jmax = nn - 1;
    float acc = 0.f;
    for (int j = 0; j < nn; j += 8) {
        float w[8], v[8];
        #pragma unroll
        for (int u = 0; u < 8; u++) {
            int jj = min(j + u, jmax);
            w[u] = sc[j + u];
            v[u] = vbase[(size_t)jj * HDIM];
        }
        #pragma unroll
        for (int u = 0; u < 8; u++) acc = fmaf(w[u], v[u], acc);
    }
    out[(size_t)i * HDIM + tid] = acc;
}

// ---------------------------------------------------------------------------
extern "C" void kernel_launch(void* const* d_in, const int* in_sizes, int n_in,
                              void* d_out, int out_size)
{
    const float* enc    = (const float*)d_in[0];
    const float* social = (const float*)d_in[1];
    const int*   starts = (const int*)  d_in[2];
    const int*   ends   = (const int*)  d_in[3];
    const float* Wq     = (const float*)d_in[4];
    const float* bq     = (const float*)d_in[5];
    const float* Wk     = (const float*)d_in[6];
    const float* bk     = (const float*)d_in[7];
    const float* Wv     = (const float*)d_in[8];
    const float* bv     = (const float*)d_in[9];
    float* out = (float*)d_out;

    const int B = in_sizes[0] / HDIM;
    const int N = in_sizes[1] / HDIM;

    __half *wk16, *wv16, *wq16;
    cudaGetSymbolAddress((void**)&wk16, g_wkt);
    cudaGetSymbolAddress((void**)&wv16, g_wvt);
    cudaGetSymbolAddress((void**)&wq16, g_wqt);

    cudaFuncSetAttribute(fused_mma_kernel, cudaFuncAttributeMaxDynamicSharedMemorySize, SMEM_BYTES);

    const float inv_sqrt_d = 1.0f / sqrtf((float)HDIM);

    // 1. Tiled transpose+convert Wk, Wv, Wq to fp16 (vectorized)
    convert_w_kernel<<<dim3(HDIM / 32, HDIM / 32, 3), 256>>>(Wk, Wv, Wq, wk16, wv16, wq16);
    // 2. K, V and Q in ONE launch (z=0:K, z=1:V, z=2:Q); 2 CTAs/SM
    fused_mma_kernel<<<dim3(HDIM / 128, N / 128, 3), 256, SMEM_BYTES>>>(
        social, enc, bk, bv, bq, inv_sqrt_d, B / 128);
    // 3. Windowed attention
    attn_kernel<<<B, 256>>>(starts, ends, out);
}